// round 8
// baseline (speedup 1.0000x reference)
#include <cuda_runtime.h>

// ---------------- problem constants (fixed shapes) ----------------
#define C_CLASSES   12
#define LOG_DHW     20                    // d*h*w = 64*128*128 = 2^20
#define DHW         (1u << LOG_DHW)
#define NPIX        (2u * DHW)            // 2,097,152
#define NPIX4       (NPIX / 4u)           // 524,288 uint4 groups
#define MIN_KEPT_K  10000u
#define IGNORE_LBL  255
#define B09_BITS    0x3F666666u           // bits of 0.9f (probs >= 0: uint order == float order)
#define NBINS       65536u                // bins on bits>>14 (prob <= 1.0 -> bin <= 64921)
#define B09_BIN     (B09_BITS >> 14)      // 64921

// ---------------- device scratch (zero-init; K3 re-zeroes each run) ----------------
__device__ unsigned int g_hcnt[NBINS];    // per-bin count of valid probs
__device__ float        g_hsum[NBINS];    // per-bin sum of nll
__device__ double       g_sumAll, g_sumB;
__device__ unsigned int g_cntAll, g_cntB;

// ==================================================================
// Kernel 1: straight-line CE map + sums + 64K-bin (cnt,sum) histogram.
// One uint4 pixel-group per thread; 12 consecutive float4 loads (front-batched).
// ==================================================================
#define K1_THREADS 256
#define K1_BLOCKS  (NPIX4 / K1_THREADS)   // 2048

__device__ __forceinline__ float pixel_lp(const float v[C_CLASSES], int l) {
    float m = v[0];
#pragma unroll
    for (int c = 1; c < C_CLASSES; c++) m = fmaxf(m, v[c]);
    float sum = 0.f, xl = 0.f;
#pragma unroll
    for (int c = 0; c < C_CLASSES; c++) {
        sum += __expf(v[c] - m);
        if (c == l) xl = v[c];
    }
    return xl - (m + __logf(sum));        // log prob at label
}

__global__ void __launch_bounds__(K1_THREADS)
compute_kernel(const float* __restrict__ pred, const int* __restrict__ tgt) {
    const int t = threadIdx.x;

    const unsigned p4 = blockIdx.x * K1_THREADS + t;      // uint4-group index
    const unsigned n  = p4 >> 18;                         // DHW/4 = 2^18 groups per image
    const unsigned s4 = p4 & 0x3FFFFu;
    const float4* base = (const float4*)(pred + (((size_t)n * C_CLASSES) << LOG_DHW)) + s4;

    float4 x[C_CLASSES];
#pragma unroll
    for (int c = 0; c < C_CLASSES; c++)
        x[c] = base[(size_t)c << 18];

    int4 lab = ((const int4*)tgt)[p4];                    // target is int32 (jax x64 disabled)

    float v[C_CLASSES];
    float lp4[4];
    int   l4[4] = { lab.x, lab.y, lab.z, lab.w };
#pragma unroll
    for (int c = 0; c < C_CLASSES; c++) v[c] = x[c].x;
    lp4[0] = pixel_lp(v, l4[0]);
#pragma unroll
    for (int c = 0; c < C_CLASSES; c++) v[c] = x[c].y;
    lp4[1] = pixel_lp(v, l4[1]);
#pragma unroll
    for (int c = 0; c < C_CLASSES; c++) v[c] = x[c].z;
    lp4[2] = pixel_lp(v, l4[2]);
#pragma unroll
    for (int c = 0; c < C_CLASSES; c++) v[c] = x[c].w;
    lp4[3] = pixel_lp(v, l4[3]);

    float    sAll = 0.f, sB = 0.f;
    unsigned cAll = 0u,  cB = 0u;
#pragma unroll
    for (int j = 0; j < 4; j++) {
        if (l4[j] != IGNORE_LBL) {
            float nll = -lp4[j];
            unsigned b = __float_as_uint(__expf(lp4[j]));   // prob bits, order-preserving
            cAll++; sAll += nll;
            if (b <= B09_BITS) { cB++; sB += nll; }
            atomicAdd(&g_hcnt[b >> 14], 1u);                // no-return RED, spread addrs
            atomicAdd(&g_hsum[b >> 14], nll);
        }
    }

    // block reduction of (sAll, sB, cAll, cB)
#pragma unroll
    for (int off = 16; off > 0; off >>= 1) {
        sAll += __shfl_down_sync(0xFFFFFFFFu, sAll, off);
        sB   += __shfl_down_sync(0xFFFFFFFFu, sB,   off);
        cAll += __shfl_down_sync(0xFFFFFFFFu, cAll, off);
        cB   += __shfl_down_sync(0xFFFFFFFFu, cB,   off);
    }
    __shared__ float    ws[16];
    __shared__ unsigned wc[16];
    int w = t >> 5;
    if ((t & 31) == 0) { ws[w] = sAll; ws[8 + w] = sB; wc[w] = cAll; wc[8 + w] = cB; }
    __syncthreads();
    if (t == 0) {
        float    SA = 0.f, SBs = 0.f;
        unsigned CA = 0u,  CBc = 0u;
#pragma unroll
        for (int i = 0; i < 8; i++) { SA += ws[i]; SBs += ws[8 + i]; CA += wc[i]; CBc += wc[8 + i]; }
        atomicAdd(&g_sumAll, (double)SA);
        atomicAdd(&g_sumB,   (double)SBs);
        atomicAdd(&g_cntAll, CA);
        atomicAdd(&g_cntB,   CBc);
    }
}

// ==================================================================
// Kernel 2: single-block selection over the 64K-bin table + loss.
// ==================================================================
#define K2_THREADS 1024
#define BINS_PER_T (NBINS / K2_THREADS)   // 64

__global__ void __launch_bounds__(K2_THREADS)
select_kernel(float* __restrict__ out) {
    __shared__ unsigned scanC[K2_THREADS];
    __shared__ float    scanSf[K2_THREADS];
    __shared__ unsigned RES_b0, RES_r, RES_cntBelow;
    __shared__ float    RES_sumBelow;
    const int t = threadIdx.x;

    const unsigned num_valid = g_cntAll;
    const unsigned keep_all  = (MIN_KEPT_K >= num_valid) ? 1u : 0u;
    const unsigned mk        = (MIN_KEPT_K < num_valid) ? MIN_KEPT_K : num_valid;
    const unsigned k         = (mk > 0u) ? (mk - 1u) : 0u;

    if (t == 0) { RES_b0 = 0u; RES_r = 0u; RES_cntBelow = 0u; RES_sumBelow = 0.f; }

    // per-thread partials over its 64 contiguous bins
    unsigned cp = 0u;
    float    sp = 0.f;
    const unsigned base = t * BINS_PER_T;
#pragma unroll
    for (int i = 0; i < BINS_PER_T / 4; i++) {
        uint4  c4 = ((const uint4*)g_hcnt)[(base >> 2) + i];
        float4 s4 = ((const float4*)g_hsum)[(base >> 2) + i];
        cp += c4.x + c4.y + c4.z + c4.w;
        sp += s4.x + s4.y + s4.z + s4.w;
    }
    scanC[t]  = cp;
    scanSf[t] = sp;
    __syncthreads();
    for (int off = 1; off < K2_THREADS; off <<= 1) {
        unsigned ac = (t >= off) ? scanC[t - off]  : 0u;
        float    as = (t >= off) ? scanSf[t - off] : 0.f;
        __syncthreads();
        scanC[t] += ac; scanSf[t] += as;
        __syncthreads();
    }
    unsigned incl = scanC[t], excl = incl - cp;

    if (mk > 0u && k >= excl && k < incl) {
        // this thread's bin range holds the kth element: walk its 64 bins
        unsigned run  = excl;
        float    srun = scanSf[t] - sp;
        for (int i = 0; i < BINS_PER_T; i++) {
            unsigned c = g_hcnt[base + i];
            if (k < run + c) {
                RES_b0       = base + i;
                RES_r        = k - run;
                RES_cntBelow = run;
                RES_sumBelow = srun;
                break;
            }
            run  += c;
            srun += g_hsum[base + i];
        }
    }
    __syncthreads();

    if (t == 0) {
        double   num; unsigned cntk;
        if (keep_all) {
            num = g_sumAll; cntk = g_cntAll;
        } else if (RES_b0 <= B09_BIN) {
            // kth prob <= ~0.9 -> threshold = 0.9 (exact path)
            num = g_sumB; cntk = g_cntB;
        } else {
            // threshold = kth prob: below-bins exact + boundary bin pro-rated
            unsigned bc = g_hcnt[RES_b0];
            float    bs = g_hsum[RES_b0];
            float    avg = (bc > 0u) ? (bs / (float)bc) : 0.f;
            num  = (double)RES_sumBelow + (double)(RES_r + 1u) * (double)avg;
            cntk = RES_cntBelow + RES_r + 1u;
        }
        unsigned denom = (cntk > 0u) ? cntk : 1u;
        out[0] = (float)(num / (double)denom);
    }
}

// ==================================================================
// Kernel 3: reset scratch for the next graph replay.
// ==================================================================
__global__ void reset_kernel() {
    unsigned i = blockIdx.x * blockDim.x + threadIdx.x;   // 65536 threads
    g_hcnt[i] = 0u;
    g_hsum[i] = 0.f;
    if (i == 0) {
        g_sumAll = 0.0; g_sumB = 0.0;
        g_cntAll = 0u;  g_cntB = 0u;
    }
}

// ---------------- launch ----------------
extern "C" void kernel_launch(void* const* d_in, const int* in_sizes, int n_in,
                              void* d_out, int out_size) {
    const float* pred = (const float*)d_in[0];
    const int*   tgt  = (const int*)d_in[1];
    float*       out  = (float*)d_out;

    compute_kernel<<<K1_BLOCKS, K1_THREADS>>>(pred, tgt);
    select_kernel<<<1, K2_THREADS>>>(out);
    reset_kernel<<<256, 256>>>();
}

// round 9
// speedup vs baseline: 3.8854x; 3.8854x over previous
#include <cuda_runtime.h>

// ---------------- problem constants (fixed shapes) ----------------
#define C_CLASSES   12
#define LOG_DHW     20                    // d*h*w = 64*128*128 = 2^20
#define DHW         (1u << LOG_DHW)
#define NPIX        (2u * DHW)            // 2,097,152
#define NPIX4       (NPIX / 4u)           // 524,288 uint4 groups
#define MIN_KEPT_K  10000u
#define IGNORE_LBL  255
#define INF_BITS    0x7F800000u
#define B09_BITS    0x3F666666u           // bits of 0.9f (probs >= 0: uint order == float order)

// ---------------- device scratch (zero-init; K3 resets each run) ----------------
__device__ unsigned int g_prob_bits[NPIX];   // prob-at-label bits; INF for invalid
__device__ unsigned int g_hist[1024];        // L0 histogram of bits>>21
__device__ unsigned int g_h1cnt[2048];       // mid-11-bit hist within L0 bin b0
__device__ float        g_h1sum[2048];
__device__ double       g_sumAll, g_sumB, g_sumL;
__device__ unsigned int g_cntAll, g_cntB, g_cntL;

// ==================================================================
// Kernel 1: straight-line CE map + L0 histogram. UNCHANGED from the
// proven R6 version (~20.5us @ 5.3 TB/s). One uint4 pixel-group/thread.
// ==================================================================
#define K1_THREADS 256
#define K1_BLOCKS  (NPIX4 / K1_THREADS)   // 2048

__device__ __forceinline__ unsigned int pixel_prob_bits(const float v[C_CLASSES], int l) {
    float m = v[0];
#pragma unroll
    for (int c = 1; c < C_CLASSES; c++) m = fmaxf(m, v[c]);
    float sum = 0.f, xl = 0.f;
#pragma unroll
    for (int c = 0; c < C_CLASSES; c++) {
        sum += __expf(v[c] - m);
        if (c == l) xl = v[c];
    }
    float lp = xl - (m + __logf(sum));
    if (l == IGNORE_LBL) return INF_BITS;      // invalid -> +inf (sorts last, like reference)
    return __float_as_uint(__expf(lp));        // prob in [0,1]
}

__global__ void __launch_bounds__(K1_THREADS)
compute_kernel(const float* __restrict__ pred, const int* __restrict__ tgt) {
    __shared__ unsigned int sh[1024];
    const int t = threadIdx.x;
    for (int i = t; i < 1024; i += K1_THREADS) sh[i] = 0u;
    __syncthreads();

    const unsigned p4 = blockIdx.x * K1_THREADS + t;      // uint4-group index
    const unsigned n  = p4 >> 18;                         // DHW/4 = 2^18 groups per image
    const unsigned s4 = p4 & 0x3FFFFu;
    const float4* base = (const float4*)(pred + (((size_t)n * C_CLASSES) << LOG_DHW)) + s4;

    float4 x[C_CLASSES];
#pragma unroll
    for (int c = 0; c < C_CLASSES; c++)
        x[c] = base[(size_t)c << 18];

    int4 lab = ((const int4*)tgt)[p4];                    // target is int32 (jax x64 disabled)

    float v[C_CLASSES];
    uint4 pb;
#pragma unroll
    for (int c = 0; c < C_CLASSES; c++) v[c] = x[c].x;
    pb.x = pixel_prob_bits(v, lab.x);
#pragma unroll
    for (int c = 0; c < C_CLASSES; c++) v[c] = x[c].y;
    pb.y = pixel_prob_bits(v, lab.y);
#pragma unroll
    for (int c = 0; c < C_CLASSES; c++) v[c] = x[c].z;
    pb.z = pixel_prob_bits(v, lab.z);
#pragma unroll
    for (int c = 0; c < C_CLASSES; c++) v[c] = x[c].w;
    pb.w = pixel_prob_bits(v, lab.w);

    ((uint4*)g_prob_bits)[p4] = pb;

    atomicAdd(&sh[pb.x >> 21], 1u);
    atomicAdd(&sh[pb.y >> 21], 1u);
    atomicAdd(&sh[pb.z >> 21], 1u);
    atomicAdd(&sh[pb.w >> 21], 1u);

    __syncthreads();
    for (int i = t; i < 1024; i += K1_THREADS) {
        unsigned c = sh[i];
        if (c) atomicAdd(&g_hist[i], c);
    }
}

// ==================================================================
// Kernel 2: batched sweep -> sums + mid-hist of boundary bin b0.
// 512 blocks x 256 thr; each thread loads 4 uint4 straight-line (MLP=4).
// ==================================================================
#define K2_THREADS 256
#define K2_BLOCKS  512                     // 512*256*4 = 524288 = NPIX4 exactly

__global__ void __launch_bounds__(K2_THREADS)
sweep_kernel() {
    __shared__ unsigned cntS[2048];
    __shared__ float    sumS[2048];
    __shared__ unsigned scanS[K2_THREADS];
    __shared__ unsigned SH_b0;
    const int t    = threadIdx.x;
    const int bid  = blockIdx.x;
    const int lane = t & 31;

    // ---- phase A: this block locates kth L0 bin b0 (g_hist in L2) ----
    {
        unsigned inv       = g_hist[1020];                 // INF_BITS>>21 = 1020
        unsigned num_valid = NPIX - inv;
        unsigned mk        = (MIN_KEPT_K < num_valid) ? MIN_KEPT_K : num_valid;
        unsigned k         = (mk > 0u) ? (mk - 1u) : 0u;

        unsigned h[4], local = 0u;
#pragma unroll
        for (int i = 0; i < 4; i++) { h[i] = g_hist[t * 4 + i]; local += h[i]; }
        scanS[t] = local;
        __syncthreads();
        for (int off = 1; off < K2_THREADS; off <<= 1) {
            unsigned add = (t >= off) ? scanS[t - off] : 0u;
            __syncthreads();
            scanS[t] += add;
            __syncthreads();
        }
        unsigned incl = scanS[t], excl = incl - local;
        if (k >= excl && k < incl) {
            unsigned run = excl;
            bool found = false;
#pragma unroll
            for (int i = 0; i < 4; i++) {
                if (!found) {
                    if (k < run + h[i]) { SH_b0 = t * 4 + i; found = true; }
                    else run += h[i];
                }
            }
        }
        __syncthreads();
    }
    const unsigned b0 = SH_b0;

    // ---- zero shared mid-hist ----
    for (int i = t; i < 2048; i += K2_THREADS) { cntS[i] = 0u; sumS[i] = 0.f; }
    __syncthreads();

    // ---- batched sweep: 4 independent uint4 loads, issued back-to-back ----
    const unsigned base4 = bid * (K2_THREADS * 4u) + t;
    uint4 a0 = ((const uint4*)g_prob_bits)[base4];
    uint4 a1 = ((const uint4*)g_prob_bits)[base4 + K2_THREADS];
    uint4 a2 = ((const uint4*)g_prob_bits)[base4 + 2u * K2_THREADS];
    uint4 a3 = ((const uint4*)g_prob_bits)[base4 + 3u * K2_THREADS];

    float    sAll = 0.f, sB = 0.f, sL = 0.f;
    unsigned cAll = 0u,  cB = 0u,  cL = 0u;

    unsigned bs[16] = { a0.x, a0.y, a0.z, a0.w,  a1.x, a1.y, a1.z, a1.w,
                        a2.x, a2.y, a2.z, a2.w,  a3.x, a3.y, a3.z, a3.w };
#pragma unroll
    for (int j = 0; j < 16; j++) {
        unsigned b = bs[j];
        if (b != INF_BITS) {
            float nll = -__logf(__uint_as_float(b));
            cAll++; sAll += nll;
            if (b <= B09_BITS) { cB++; sB += nll; }
            unsigned bin = b >> 21;
            if (bin < b0)       { cL++; sL += nll; }
            else if (bin == b0) {
                unsigned mid = (b >> 10) & 0x7FFu;
                atomicAdd(&cntS[mid], 1u);
                atomicAdd(&sumS[mid], nll);
            }
        }
    }

    // ---- block reduction of 6 accumulators ----
#pragma unroll
    for (int off = 16; off > 0; off >>= 1) {
        sAll += __shfl_down_sync(0xFFFFFFFFu, sAll, off);
        sB   += __shfl_down_sync(0xFFFFFFFFu, sB,   off);
        sL   += __shfl_down_sync(0xFFFFFFFFu, sL,   off);
        cAll += __shfl_down_sync(0xFFFFFFFFu, cAll, off);
        cB   += __shfl_down_sync(0xFFFFFFFFu, cB,   off);
        cL   += __shfl_down_sync(0xFFFFFFFFu, cL,   off);
    }
    float*    ws = (float*)scanS;           // reuse scan space
    unsigned* wc = (unsigned*)scanS + 24;
    int w = t >> 5;
    if (lane == 0) {
        ws[w] = sAll; ws[8 + w] = sB; ws[16 + w] = sL;
        wc[w] = cAll; wc[8 + w] = cB; wc[16 + w] = cL;
    }
    __syncthreads();
    if (t == 0) {
        float    SA = 0.f, SBs = 0.f, SL = 0.f;
        unsigned CA = 0u,  CBc = 0u, CL = 0u;
#pragma unroll
        for (int i = 0; i < 8; i++) {
            SA += ws[i]; SBs += ws[8 + i]; SL += ws[16 + i];
            CA += wc[i]; CBc += wc[8 + i]; CL += wc[16 + i];
        }
        atomicAdd(&g_sumAll, (double)SA);
        atomicAdd(&g_sumB,   (double)SBs);
        atomicAdd(&g_sumL,   (double)SL);
        atomicAdd(&g_cntAll, CA);
        atomicAdd(&g_cntB,   CBc);
        atomicAdd(&g_cntL,   CL);
    }

    // ---- flush shared mid-hist (distinct addresses, sparse) ----
    for (int i = t; i < 2048; i += K2_THREADS) {
        unsigned c = cntS[i];
        if (c) { atomicAdd(&g_h1cnt[i], c); atomicAdd(&g_h1sum[i], sumS[i]); }
    }
}

// ==================================================================
// Kernel 3: finalize (1 block) + reset scratch for next graph replay.
// ==================================================================
#define K3_THREADS 1024

__global__ void __launch_bounds__(K3_THREADS)
finalize_kernel(float* __restrict__ out) {
    __shared__ unsigned scanC[K3_THREADS];
    __shared__ float    scanF[K3_THREADS];
    __shared__ unsigned SH_b0, SH_r, SH_b1, SH_r2, SH_cb1;
    __shared__ float    SH_sb1;
    const int t = threadIdx.x;

    const unsigned inv       = g_hist[1020];
    const unsigned num_valid = NPIX - inv;
    const unsigned keep_all  = (MIN_KEPT_K >= num_valid) ? 1u : 0u;
    const unsigned mk        = (MIN_KEPT_K < num_valid) ? MIN_KEPT_K : num_valid;
    const unsigned k         = (mk > 0u) ? (mk - 1u) : 0u;

    // ---- locate b0 + rank r in L0 hist (1024 bins, 1 per thread) ----
    {
        unsigned local = g_hist[t];
        scanC[t] = local;
        __syncthreads();
        for (int off = 1; off < K3_THREADS; off <<= 1) {
            unsigned add = (t >= off) ? scanC[t - off] : 0u;
            __syncthreads();
            scanC[t] += add;
            __syncthreads();
        }
        unsigned incl = scanC[t], excl = incl - local;
        if (k >= excl && k < incl) { SH_b0 = (unsigned)t; SH_r = k - excl; }
        __syncthreads();
    }
    const unsigned r = SH_r;

    // ---- locate b1 + rank r2 in the mid hist (2048 bins, 2 per thread) ----
    {
        unsigned c0 = g_h1cnt[2 * t], c1 = g_h1cnt[2 * t + 1];
        float    s0 = g_h1sum[2 * t], s1 = g_h1sum[2 * t + 1];
        unsigned local = c0 + c1;
        scanC[t] = local;
        scanF[t] = s0 + s1;
        __syncthreads();
        for (int off = 1; off < K3_THREADS; off <<= 1) {
            unsigned ac = (t >= off) ? scanC[t - off] : 0u;
            float    as = (t >= off) ? scanF[t - off] : 0.f;
            __syncthreads();
            scanC[t] += ac; scanF[t] += as;
            __syncthreads();
        }
        unsigned incl = scanC[t], excl = incl - local;
        if (r >= excl && r < incl) {
            float sbase = scanF[t] - (s0 + s1);
            if (r < excl + c0) { SH_b1 = 2u * t;     SH_r2 = r - excl;      SH_cb1 = excl;      SH_sb1 = sbase; }
            else               { SH_b1 = 2u * t + 1; SH_r2 = r - excl - c0; SH_cb1 = excl + c0; SH_sb1 = sbase + s0; }
        }
        __syncthreads();
    }

    if (t == 0) {
        const unsigned b0 = SH_b0, b1 = SH_b1, r2 = SH_r2;
        const unsigned kth21 = (b0 << 11) | b1;          // kth value to 21-bit precision
        double   num; unsigned cntk;
        if (keep_all) {
            num = g_sumAll; cntk = g_cntAll;
        } else if (kth21 <= (B09_BITS >> 10)) {
            // kth prob <= 0.9 -> threshold = 0.9 (exact path; the actual data path)
            num = g_sumB; cntk = g_cntB;
        } else {
            // threshold = kth prob: exact below-bins + boundary mid-bin pro-rated
            unsigned bc = g_h1cnt[b1];
            float    avg = (bc > 0u) ? (g_h1sum[b1] / (float)bc) : 0.f;
            num  = g_sumL + (double)SH_sb1 + (double)(r2 + 1u) * (double)avg;
            cntk = g_cntL + SH_cb1 + r2 + 1u;
        }
        unsigned denom = (cntk > 0u) ? cntk : 1u;
        out[0] = (float)(num / (double)denom);
    }

    // ---- reset scratch for next replay (all reads above are done) ----
    __syncthreads();
    if (t < 1024) g_hist[t] = 0u;
    g_h1cnt[t] = 0u;          g_h1sum[t] = 0.f;
    g_h1cnt[t + 1024] = 0u;   g_h1sum[t + 1024] = 0.f;
    if (t == 0) {
        g_sumAll = 0.0; g_sumB = 0.0; g_sumL = 0.0;
        g_cntAll = 0u;  g_cntB = 0u;  g_cntL = 0u;
    }
}

// ---------------- launch ----------------
extern "C" void kernel_launch(void* const* d_in, const int* in_sizes, int n_in,
                              void* d_out, int out_size) {
    const float* pred = (const float*)d_in[0];
    const int*   tgt  = (const int*)d_in[1];
    float*       out  = (float*)d_out;

    compute_kernel<<<K1_BLOCKS, K1_THREADS>>>(pred, tgt);
    sweep_kernel<<<K2_BLOCKS, K2_THREADS>>>();
    finalize_kernel<<<1, K3_THREADS>>>(out);
}